// round 7
// baseline (speedup 1.0000x reference)
#include <cuda_runtime.h>
#include <cstdint>

#define TPB     256
#define NBLOCKS 912      // 152 SMs * 6 resident blocks (smem-limited)
#define W       512      // column-strip width (= 2 * TPB)
#define DEPTH   4        // pipeline stages
#define ROWS    4        // rows per stage
#define CPW     130      // 16B chunks per row window (520 floats >= 512+3 shift)
#define ROWBUF  (CPW * 4)        // 520 floats per row buffer
#define STAGEF  (ROWS * ROWBUF)  // 2080 floats per stage

// ---------------------------------------------------------------------------
// out = sum_j x[j] * ( c1[j] + sum_{i<j} x[i] * c2[base(i) + (j-i-1)] )
// Work unit = row-segment (row i x 512-col strip), element-balanced across
// blocks. Coeff segments stream through a DEPTH-stage cp.async pipeline into
// smem (16B-aligned global requests, ~25KB in flight per block), compute
// reads smem at the row-uniform shift. Register accumulator per column.
// ---------------------------------------------------------------------------

__global__ void zero_out_kernel(float* out) {
    if (threadIdx.x == 0 && blockIdx.x == 0) out[0] = 0.0f;
}

__device__ __forceinline__ float warp_sum(float v) {
    #pragma unroll
    for (int o = 16; o > 0; o >>= 1) v += __shfl_down_sync(0xffffffffu, v, o);
    return v;
}

__device__ __forceinline__ void cp16(uint32_t dst_smem, const float* src) {
    asm volatile("cp.async.cg.shared.global [%0], [%1], 16;\n"
                 :: "r"(dst_smem), "l"(__cvta_generic_to_global(src)));
}
#define CP_COMMIT() asm volatile("cp.async.commit_group;\n" ::: "memory")
#define CP_WAIT(N)  asm volatile("cp.async.wait_group %0;\n" :: "n"(N) : "memory")

__global__ __launch_bounds__(TPB)
void ham_kernel(const float* __restrict__ x,
                const float* __restrict__ c,
                float* __restrict__ out,
                int n) {
    __shared__ __align__(16) float buf[DEPTH * STAGEF];   // 33280 B
    __shared__ float wsum[TPB / 32];

    const int t = threadIdx.x;
    const int b = blockIdx.x;
    const int G = gridDim.x;
    const float* c2 = c + n;
    const int total = (n * (n - 1)) >> 1;        // 33,550,336

    const int ns = n / W;                        // 16 strips
    const int U  = W * (ns * (ns + 1) / 2) - ns; // 69616 row-segments
    const int u0 = (int)(((long long)b       * U) / G);
    const int u1 = (int)(((long long)(b + 1) * U) / G);

    float sum = 0.0f;

    // degree-1 terms, spread over all blocks
    for (int k = b * TPB + t; k < n; k += G * TPB)
        sum += __ldg(x + k) * __ldg(c + k);

    // fixed chunk -> (row, col16) map for this thread (520 chunks per stage)
    const int r0 = t / CPW,            c0 = t - r0 * CPW;
    const int k1 = t + TPB;
    const int r1 = k1 / CPW,           c1 = k1 - r1 * CPW;
    const int k2 = t + 2 * TPB;
    const bool has2 = (k2 < ROWS * CPW);
    const int r2 = k2 / CPW,           c2i = k2 - r2 * CPW;

    // locate starting strip for unit u0
    int js = 0, Pjs = 0;
    while (Pjs + ((js + 1) * W - 1) <= u0) { Pjs += (js + 1) * W - 1; ++js; }
    int i = u0 - Pjs;
    int u = u0;

    while (u < u1) {
        const int K   = (js + 1) * W - 1;
        const int j0  = js * W;
        const int j_a = j0 + t;
        const int j_b = j_a + TPB;
        int iend = i + (u1 - u); if (iend > K) iend = K;
        const int nst = (iend - i + ROWS - 1) / ROWS;

        // producer / consumer row state (segment start s(i), recurrence
        // s(i+1) = s(i) + n-2-i), s = base(i) + j0 - i - 1
        int ip = i, sp = ((i * (2 * n - 1 - i)) >> 1) + j0 - i - 1;
        int ic = i, sc = sp;

        float acc0 = 0.0f, acc1 = 0.0f;

        auto produce = [&](int st) {
            if (st >= nst) return;
            const int pr = iend - ip < ROWS ? iend - ip : ROWS;
            int sr[ROWS], ir[ROWS];
            {
                int ss = sp, ii = ip;
                #pragma unroll
                for (int r = 0; r < ROWS; ++r) {
                    sr[r] = ss; ir[r] = ii;
                    ss += n - 2 - ii; ++ii;
                }
                sp = ss; ip += ROWS;   // only last stage under-uses; unused after
            }
            float* dst = buf + (st % DEPTH) * STAGEF;
            auto emit = [&](int rr, int cc) {
                if (rr >= pr) return;
                const int s_r = sr[rr];
                const int a   = s_r & ~3;
                const int row = ir[rr];
                int lo = 0;
                if (row >= j0) lo = (s_r & 3) + (row + 1 - j0);
                const int cb4 = 4 * cc;
                if (cb4 + 3 < lo) return;          // chunk entirely below diag
                int g = a + cb4;
                if (g > total - 4) g = total - 4;  // clamp at array end
                cp16((uint32_t)__cvta_generic_to_shared(dst + rr * ROWBUF + cb4),
                     c2 + g);
            };
            emit(r0, c0);
            emit(r1, c1);
            if (has2) emit(r2, c2i);
        };

        // prologue
        #pragma unroll
        for (int st = 0; st < DEPTH - 1; ++st) { produce(st); CP_COMMIT(); }

        for (int st = 0; st < nst; ++st) {
            produce(st + DEPTH - 1); CP_COMMIT();
            CP_WAIT(DEPTH - 1);
            __syncthreads();
            // consume stage st
            {
                const int cr = iend - ic < ROWS ? iend - ic : ROWS;
                const float* src = buf + (st % DEPTH) * STAGEF;
                #pragma unroll
                for (int r = 0; r < ROWS; ++r) {
                    if (r >= cr) break;
                    const int row = ic + r;
                    const int off = sc & 3;
                    const float xi = __ldg(x + row);
                    float ca = src[r * ROWBUF + off + t];
                    float cb = src[r * ROWBUF + off + t + TPB];
                    if (j_a <= row) ca = 0.0f;
                    if (j_b <= row) cb = 0.0f;
                    acc0 = fmaf(xi, ca, acc0);
                    acc1 = fmaf(xi, cb, acc1);
                    sc += n - 2 - row;
                }
                ic += cr;
            }
            __syncthreads();
        }

        sum += acc0 * __ldg(x + j_a) + acc1 * __ldg(x + j_b);

        i = iend; u = Pjs + i;
        if (i == K) { Pjs += K; ++js; i = 0; }
    }

    // block reduction: warp shuffle -> smem -> warp 0 -> one atomic per block
    float w = warp_sum(sum);
    if ((t & 31) == 0) wsum[t >> 5] = w;
    __syncthreads();
    if (t < 32) {
        float v = (t < TPB / 32) ? wsum[t] : 0.0f;
        v = warp_sum(v);
        if (t == 0) atomicAdd(out, v);
    }
}

extern "C" void kernel_launch(void* const* d_in, const int* in_sizes, int n_in,
                              void* d_out, int out_size) {
    const float* x = (const float*)d_in[0];
    const float* c = (const float*)d_in[1];
    float* out = (float*)d_out;
    const int n = in_sizes[0];   // 8192

    zero_out_kernel<<<1, 32>>>(out);
    ham_kernel<<<NBLOCKS, TPB>>>(x, c, out, n);
}